// round 1
// baseline (speedup 1.0000x reference)
#include <cuda_runtime.h>
#include <cuda_bf16.h>
#include <math.h>

// ----------------------------------------------------------------------------
// GAT_cat_decoder: 2-layer GATConv (PyG semantics, add_self_loops) + linear.
// N=50000 nodes, E=1600000 edges, IN=64, HID=16, HEADS=4, OUT=1.
// Strategy: global-max-shifted softmax (shift-invariant, removes segment-max
// edge pass), float4 vector RED atomics for scatter, everything resident in L2.
// ----------------------------------------------------------------------------

#define NN 50000
#define EE 1600000
#define ATT_SLOPE 0.2f
#define ACT_SLOPE 0.01f

// ---- device scratch (static, no allocation) ----
__device__ __align__(16) float g_h1[NN * 64];
__device__ __align__(16) float g_out1[NN * 64];
__device__ __align__(16) float g_as1[NN * 4];
__device__ __align__(16) float g_ad1[NN * 4];
__device__ __align__(16) float g_den1[NN * 4];
__device__ __align__(16) float g_h2[NN * 16];
__device__ __align__(16) float g_out2[NN * 16];
__device__ __align__(16) float g_as2[NN];
__device__ __align__(16) float g_ad2[NN];
__device__ __align__(16) float g_den2[NN];
__device__ int g_src[EE];
__device__ int g_dst[EE];
// reduction scratch: [0..3] max_as1, [4..7] max_ad1, [8] max_as2, [9] max_ad2
__device__ float g_red[12];
// shifts: [0..3] M1 per head, [4] M2
__device__ __align__(16) float g_M[8];
__device__ int g_is64;

__device__ __forceinline__ float lrelu(float x, float s) {
    return x > 0.f ? x : s * x;
}

__device__ __forceinline__ void atomicMaxF(float* a, float v) {
    if (v >= 0.f) atomicMax((int*)a, __float_as_int(v));
    else          atomicMin((unsigned int*)a, __float_as_uint(v));
}

// ---- edge index dtype detection + conversion ----
__global__ void k_detect(const long long* __restrict__ e) {
    int t = threadIdx.x;
    int bad = 0;
    const int SAMPLES = 2048;
    long long stride = (long long)EE / SAMPLES;   // stay within first EE int64 slots
    for (int i = t; i < SAMPLES; i += 256) {
        long long v = e[(long long)i * stride];
        if (v < 0 || v >= NN) bad = 1;
    }
    bad = __syncthreads_or(bad);
    if (t == 0) g_is64 = bad ? 0 : 1;
}

__global__ void k_convert(const void* __restrict__ eraw) {
    int i = blockIdx.x * blockDim.x + threadIdx.x;
    if (i >= EE) return;
    if (g_is64) {
        const long long* e = (const long long*)eraw;
        g_src[i] = (int)e[i];
        g_dst[i] = (int)e[EE + i];
    } else {
        const int* e = (const int*)eraw;
        g_src[i] = e[i];
        g_dst[i] = e[EE + i];
    }
}

// ---- per-launch state reset ----
__global__ void k_init() {
    int i = blockIdx.x * blockDim.x + threadIdx.x;
    float4 z = make_float4(0.f, 0.f, 0.f, 0.f);
    if (i < NN * 16) ((float4*)g_out1)[i] = z;       // NN*64 floats
    if (i < NN * 4)  ((float4*)g_out2)[i] = z;       // NN*16 floats
    if (i < NN)      ((float4*)g_den1)[i] = z;       // NN*4 floats
    if (i < NN)      g_den2[i] = 0.f;
    if (i < 12)      g_red[i] = -INFINITY;
}

// ---- layer 1 GEMM: h1 = x @ W1 (64 -> 64) ----
__global__ void k_gemm1(const float* __restrict__ x, const float* __restrict__ W) {
    __shared__ float Ws[64][64];
    __shared__ float Xs[64][64];
    int tid = threadIdx.x;                  // 256
    for (int i = tid; i < 64 * 64; i += 256) Ws[i >> 6][i & 63] = W[i];
    int base = blockIdx.x * 64;
    for (int i = tid; i < 64 * 64; i += 256) {
        int r = i >> 6, c = i & 63;
        int node = base + r;
        Xs[r][c] = (node < NN) ? x[node * 64 + c] : 0.f;
    }
    __syncthreads();
    int tx = tid & 63;       // out col
    int ty = tid >> 6;       // 0..3
    float acc[16];
    #pragma unroll
    for (int i = 0; i < 16; i++) acc[i] = 0.f;
    for (int k = 0; k < 64; k++) {
        float w = Ws[k][tx];
        #pragma unroll
        for (int i = 0; i < 16; i++) acc[i] += Xs[ty + 4 * i][k] * w;
    }
    #pragma unroll
    for (int i = 0; i < 16; i++) {
        int node = base + ty + 4 * i;
        if (node < NN) g_h1[node * 64 + tx] = acc[i];
    }
}

// ---- layer 1 attention logits per (node, head) ----
__global__ void k_alpha1(const float* __restrict__ asrc, const float* __restrict__ adst) {
    int idx = blockIdx.x * blockDim.x + threadIdx.x;
    if (idx >= NN * 4) return;
    int node = idx >> 2, head = idx & 3;
    const float4* hp = (const float4*)(g_h1 + node * 64 + head * 16);
    const float4* ap = (const float4*)(asrc + head * 16);
    const float4* dp = (const float4*)(adst + head * 16);
    float s = 0.f, d = 0.f;
    #pragma unroll
    for (int j = 0; j < 4; j++) {
        float4 h = hp[j], a = ap[j], b = dp[j];
        s += h.x * a.x + h.y * a.y + h.z * a.z + h.w * a.w;
        d += h.x * b.x + h.y * b.y + h.z * b.z + h.w * b.w;
    }
    g_as1[idx] = s;
    g_ad1[idx] = d;
}

// ---- global max reduce (layer 1, per head) ----
__global__ void k_maxred1() {
    int tid = blockIdx.x * blockDim.x + threadIdx.x;
    int stride = gridDim.x * blockDim.x;     // multiple of 4
    float ms = -INFINITY, md = -INFINITY;
    for (int i = tid; i < NN * 4; i += stride) {
        ms = fmaxf(ms, g_as1[i]);
        md = fmaxf(md, g_ad1[i]);
    }
    // lanes with same (lane&3) hold same head
    #pragma unroll
    for (int off = 16; off >= 4; off >>= 1) {
        ms = fmaxf(ms, __shfl_xor_sync(0xffffffffu, ms, off));
        md = fmaxf(md, __shfl_xor_sync(0xffffffffu, md, off));
    }
    __shared__ float ss[8][4], sd[8][4];
    int warp = threadIdx.x >> 5, lane = threadIdx.x & 31;
    if (lane < 4) { ss[warp][lane] = ms; sd[warp][lane] = md; }
    __syncthreads();
    if (threadIdx.x < 4) {
        float a = -INFINITY, b = -INFINITY;
        for (int w = 0; w < 8; w++) {
            a = fmaxf(a, ss[w][threadIdx.x]);
            b = fmaxf(b, sd[w][threadIdx.x]);
        }
        atomicMaxF(&g_red[threadIdx.x], a);
        atomicMaxF(&g_red[4 + threadIdx.x], b);
    }
}

__global__ void k_M1() {
    int t = threadIdx.x;
    if (t < 4) g_M[t] = lrelu(g_red[t] + g_red[4 + t], ATT_SLOPE);
}

// ---- layer 1 denominator: edges then self-loops ----
__global__ void k_edgeB1() {
    int e = blockIdx.x * blockDim.x + threadIdx.x;
    if (e >= EE) return;
    int s = g_src[e], d = g_dst[e];
    float4 as = *(const float4*)(g_as1 + s * 4);
    float4 ad = *(const float4*)(g_ad1 + d * 4);
    float4 M = *(const float4*)(g_M);
    float4 w;
    w.x = __expf(lrelu(as.x + ad.x, ATT_SLOPE) - M.x);
    w.y = __expf(lrelu(as.y + ad.y, ATT_SLOPE) - M.y);
    w.z = __expf(lrelu(as.z + ad.z, ATT_SLOPE) - M.z);
    w.w = __expf(lrelu(as.w + ad.w, ATT_SLOPE) - M.w);
    atomicAdd((float4*)(g_den1 + d * 4), w);
}

__global__ void k_selfB1() {
    int idx = blockIdx.x * blockDim.x + threadIdx.x;
    if (idx >= NN * 4) return;
    g_den1[idx] += __expf(lrelu(g_as1[idx] + g_ad1[idx], ATT_SLOPE) - g_M[idx & 3]);
}

// ---- layer 1 weighted scatter: 16 lanes per edge, one float4 each ----
__global__ void k_edgeC1() {
    int gid = blockIdx.x * blockDim.x + threadIdx.x;
    int e = gid >> 4;
    if (e >= EE) return;
    int lane16 = threadIdx.x & 15;
    int head = lane16 >> 2;
    int s = g_src[e], d = g_dst[e];
    float as = g_as1[s * 4 + head];
    float ad = g_ad1[d * 4 + head];
    float den = g_den1[d * 4 + head];
    float alpha = __expf(lrelu(as + ad, ATT_SLOPE) - g_M[head]) / den;
    float4 hv = *(const float4*)(g_h1 + s * 64 + lane16 * 4);
    hv.x *= alpha; hv.y *= alpha; hv.z *= alpha; hv.w *= alpha;
    atomicAdd((float4*)(g_out1 + d * 64 + lane16 * 4), hv);
}

// ---- layer 1 epilogue: self-loop contribution + bias + leaky ----
__global__ void k_post1(const float* __restrict__ b1) {
    int idx = blockIdx.x * blockDim.x + threadIdx.x;
    if (idx >= NN * 16) return;
    int node = idx >> 4, c4 = idx & 15, head = c4 >> 2;
    int nh = node * 4 + head;
    float alpha = __expf(lrelu(g_as1[nh] + g_ad1[nh], ATT_SLOPE) - g_M[head]) / g_den1[nh];
    float4 o = ((float4*)g_out1)[idx];
    float4 h = ((const float4*)g_h1)[idx];
    float4 b = ((const float4*)b1)[c4];
    o.x = lrelu(o.x + h.x * alpha + b.x, ACT_SLOPE);
    o.y = lrelu(o.y + h.y * alpha + b.y, ACT_SLOPE);
    o.z = lrelu(o.z + h.z * alpha + b.z, ACT_SLOPE);
    o.w = lrelu(o.w + h.w * alpha + b.w, ACT_SLOPE);
    ((float4*)g_out1)[idx] = o;
}

// ---- layer 2 GEMM: h2 = act1 @ W2 (64 -> 16) ----
__global__ void k_gemm2(const float* __restrict__ W) {
    __shared__ float Ws[64][16];
    __shared__ float Xs[64][64];
    int tid = threadIdx.x;
    for (int i = tid; i < 64 * 16; i += 256) Ws[i >> 4][i & 15] = W[i];
    int base = blockIdx.x * 64;
    for (int i = tid; i < 64 * 64; i += 256) {
        int r = i >> 6, c = i & 63;
        int node = base + r;
        Xs[r][c] = (node < NN) ? g_out1[node * 64 + c] : 0.f;
    }
    __syncthreads();
    int tx = tid & 15;       // out col
    int ty = tid >> 4;       // 0..15
    float acc[4] = {0.f, 0.f, 0.f, 0.f};
    for (int k = 0; k < 64; k++) {
        float w = Ws[k][tx];
        #pragma unroll
        for (int i = 0; i < 4; i++) acc[i] += Xs[ty + 16 * i][k] * w;
    }
    #pragma unroll
    for (int i = 0; i < 4; i++) {
        int node = base + ty + 16 * i;
        if (node < NN) g_h2[node * 16 + tx] = acc[i];
    }
}

__global__ void k_alpha2(const float* __restrict__ asrc, const float* __restrict__ adst) {
    int node = blockIdx.x * blockDim.x + threadIdx.x;
    if (node >= NN) return;
    const float4* hp = (const float4*)(g_h2 + node * 16);
    const float4* ap = (const float4*)asrc;
    const float4* dp = (const float4*)adst;
    float s = 0.f, d = 0.f;
    #pragma unroll
    for (int j = 0; j < 4; j++) {
        float4 h = hp[j], a = ap[j], b = dp[j];
        s += h.x * a.x + h.y * a.y + h.z * a.z + h.w * a.w;
        d += h.x * b.x + h.y * b.y + h.z * b.z + h.w * b.w;
    }
    g_as2[node] = s;
    g_ad2[node] = d;
}

__global__ void k_maxred2() {
    int tid = blockIdx.x * blockDim.x + threadIdx.x;
    int stride = gridDim.x * blockDim.x;
    float ms = -INFINITY, md = -INFINITY;
    for (int i = tid; i < NN; i += stride) {
        ms = fmaxf(ms, g_as2[i]);
        md = fmaxf(md, g_ad2[i]);
    }
    #pragma unroll
    for (int off = 16; off >= 1; off >>= 1) {
        ms = fmaxf(ms, __shfl_xor_sync(0xffffffffu, ms, off));
        md = fmaxf(md, __shfl_xor_sync(0xffffffffu, md, off));
    }
    __shared__ float ss[8], sd[8];
    int warp = threadIdx.x >> 5, lane = threadIdx.x & 31;
    if (lane == 0) { ss[warp] = ms; sd[warp] = md; }
    __syncthreads();
    if (threadIdx.x == 0) {
        float a = -INFINITY, b = -INFINITY;
        for (int w = 0; w < 8; w++) { a = fmaxf(a, ss[w]); b = fmaxf(b, sd[w]); }
        atomicMaxF(&g_red[8], a);
        atomicMaxF(&g_red[9], b);
    }
}

__global__ void k_M2() {
    g_M[4] = lrelu(g_red[8] + g_red[9], ATT_SLOPE);
}

__global__ void k_edgeB2() {
    int e = blockIdx.x * blockDim.x + threadIdx.x;
    if (e >= EE) return;
    int s = g_src[e], d = g_dst[e];
    float w = __expf(lrelu(g_as2[s] + g_ad2[d], ATT_SLOPE) - g_M[4]);
    atomicAdd(&g_den2[d], w);
}

__global__ void k_selfB2() {
    int node = blockIdx.x * blockDim.x + threadIdx.x;
    if (node >= NN) return;
    g_den2[node] += __expf(lrelu(g_as2[node] + g_ad2[node], ATT_SLOPE) - g_M[4]);
}

// ---- layer 2 weighted scatter: 4 lanes per edge ----
__global__ void k_edgeC2() {
    int gid = blockIdx.x * blockDim.x + threadIdx.x;
    int e = gid >> 2;
    if (e >= EE) return;
    int lane4 = threadIdx.x & 3;
    int s = g_src[e], d = g_dst[e];
    float alpha = __expf(lrelu(g_as2[s] + g_ad2[d], ATT_SLOPE) - g_M[4]) / g_den2[d];
    float4 hv = ((const float4*)(g_h2 + s * 16))[lane4];
    hv.x *= alpha; hv.y *= alpha; hv.z *= alpha; hv.w *= alpha;
    atomicAdd(((float4*)(g_out2 + d * 16)) + lane4, hv);
}

// ---- final: self-loop + bias + leaky + linear -> out ----
__global__ void k_final(const float* __restrict__ b2, const float* __restrict__ Wo,
                        const float* __restrict__ bo, float* __restrict__ out) {
    int node = blockIdx.x * blockDim.x + threadIdx.x;
    if (node >= NN) return;
    float alpha = __expf(lrelu(g_as2[node] + g_ad2[node], ATT_SLOPE) - g_M[4]) / g_den2[node];
    const float4* Wo4 = (const float4*)Wo;
    const float4* b24 = (const float4*)b2;
    float acc = 0.f;
    #pragma unroll
    for (int j = 0; j < 4; j++) {
        float4 o = ((float4*)g_out2)[node * 4 + j];
        float4 h = ((const float4*)g_h2)[node * 4 + j];
        float4 b = b24[j];
        float4 w = Wo4[j];
        acc += lrelu(o.x + h.x * alpha + b.x, ACT_SLOPE) * w.x;
        acc += lrelu(o.y + h.y * alpha + b.y, ACT_SLOPE) * w.y;
        acc += lrelu(o.z + h.z * alpha + b.z, ACT_SLOPE) * w.z;
        acc += lrelu(o.w + h.w * alpha + b.w, ACT_SLOPE) * w.w;
    }
    out[node] = acc + bo[0];
}

extern "C" void kernel_launch(void* const* d_in, const int* in_sizes, int n_in,
                              void* d_out, int out_size) {
    const float* x   = (const float*)d_in[0];
    const void*  ei  = d_in[1];
    const float* W1  = (const float*)d_in[2];
    const float* a_s1 = (const float*)d_in[3];
    const float* a_d1 = (const float*)d_in[4];
    const float* b1  = (const float*)d_in[5];
    const float* W2  = (const float*)d_in[6];
    const float* a_s2 = (const float*)d_in[7];
    const float* a_d2 = (const float*)d_in[8];
    const float* b2  = (const float*)d_in[9];
    const float* Wo  = (const float*)d_in[10];
    const float* bo  = (const float*)d_in[11];
    float* out = (float*)d_out;

    k_detect<<<1, 256>>>((const long long*)ei);
    k_convert<<<(EE + 255) / 256, 256>>>(ei);
    k_init<<<(NN * 16 + 255) / 256, 256>>>();

    // layer 1
    k_gemm1<<<(NN + 63) / 64, 256>>>(x, W1);
    k_alpha1<<<(NN * 4 + 255) / 256, 256>>>(a_s1, a_d1);
    k_maxred1<<<200, 256>>>();
    k_M1<<<1, 32>>>();
    k_edgeB1<<<(EE + 255) / 256, 256>>>();
    k_selfB1<<<(NN * 4 + 255) / 256, 256>>>();
    k_edgeC1<<<(EE * 16 + 255) / 256, 256>>>();
    k_post1<<<(NN * 16 + 255) / 256, 256>>>(b1);

    // layer 2
    k_gemm2<<<(NN + 63) / 64, 256>>>(W2);
    k_alpha2<<<(NN + 255) / 256, 256>>>(a_s2, a_d2);
    k_maxred2<<<200, 256>>>();
    k_M2<<<1, 1>>>();
    k_edgeB2<<<(EE + 255) / 256, 256>>>();
    k_selfB2<<<(NN + 255) / 256, 256>>>();
    k_edgeC2<<<(EE * 4 + 255) / 256, 256>>>();

    k_final<<<(NN + 255) / 256, 256>>>(b2, Wo, bo, out);
}

// round 2
// speedup vs baseline: 1.0137x; 1.0137x over previous
#include <cuda_runtime.h>
#include <cuda_bf16.h>
#include <math.h>

// ----------------------------------------------------------------------------
// GAT_cat_decoder: 2-layer GATConv (PyG semantics, add_self_loops) + linear.
// N=50000 nodes, E=1600000 edges, IN=64, HID=16, HEADS=4, OUT=1.
// Strategy: global-max-shifted softmax (shift-invariant, removes segment-max
// edge pass), float4 vector RED atomics for scatter, everything resident in L2.
// ----------------------------------------------------------------------------

#define NN 50000
#define EE 1600000
#define ATT_SLOPE 0.2f
#define ACT_SLOPE 0.01f

// ---- device scratch (static, no allocation) ----
__device__ __align__(16) float g_h1[NN * 64];
__device__ __align__(16) float g_out1[NN * 64];
__device__ __align__(16) float g_as1[NN * 4];
__device__ __align__(16) float g_ad1[NN * 4];
__device__ __align__(16) float g_den1[NN * 4];
__device__ __align__(16) float g_h2[NN * 16];
__device__ __align__(16) float g_out2[NN * 16];
__device__ __align__(16) float g_as2[NN];
__device__ __align__(16) float g_ad2[NN];
__device__ __align__(16) float g_den2[NN];
__device__ int g_src[EE];
__device__ int g_dst[EE];
// reduction scratch: [0..3] max_as1, [4..7] max_ad1, [8] max_as2, [9] max_ad2
__device__ float g_red[12];
// shifts: [0..3] M1 per head, [4] M2
__device__ __align__(16) float g_M[8];
__device__ int g_is64;

__device__ __forceinline__ float lrelu(float x, float s) {
    return x > 0.f ? x : s * x;
}

__device__ __forceinline__ void atomicMaxF(float* a, float v) {
    if (v >= 0.f) atomicMax((int*)a, __float_as_int(v));
    else          atomicMin((unsigned int*)a, __float_as_uint(v));
}

// ---- edge index dtype detection + conversion ----
__global__ void k_detect(const long long* __restrict__ e) {
    int t = threadIdx.x;
    int bad = 0;
    const int SAMPLES = 2048;
    long long stride = (long long)EE / SAMPLES;   // stay within first EE int64 slots
    for (int i = t; i < SAMPLES; i += 256) {
        long long v = e[(long long)i * stride];
        if (v < 0 || v >= NN) bad = 1;
    }
    bad = __syncthreads_or(bad);
    if (t == 0) g_is64 = bad ? 0 : 1;
}

__global__ void k_convert(const void* __restrict__ eraw) {
    int i = blockIdx.x * blockDim.x + threadIdx.x;
    if (i >= EE) return;
    if (g_is64) {
        const long long* e = (const long long*)eraw;
        g_src[i] = (int)e[i];
        g_dst[i] = (int)e[EE + i];
    } else {
        const int* e = (const int*)eraw;
        g_src[i] = e[i];
        g_dst[i] = e[EE + i];
    }
}

// ---- per-launch state reset ----
__global__ void k_init() {
    int i = blockIdx.x * blockDim.x + threadIdx.x;
    float4 z = make_float4(0.f, 0.f, 0.f, 0.f);
    if (i < NN * 16) ((float4*)g_out1)[i] = z;       // NN*64 floats
    if (i < NN * 4)  ((float4*)g_out2)[i] = z;       // NN*16 floats
    if (i < NN)      ((float4*)g_den1)[i] = z;       // NN*4 floats
    if (i < NN)      g_den2[i] = 0.f;
    if (i < 12)      g_red[i] = -INFINITY;
}

// ---- layer 1 GEMM: h1 = x @ W1 (64 -> 64) ----
__global__ void k_gemm1(const float* __restrict__ x, const float* __restrict__ W) {
    __shared__ float Ws[64][64];
    __shared__ float Xs[64][64];
    int tid = threadIdx.x;                  // 256
    for (int i = tid; i < 64 * 64; i += 256) Ws[i >> 6][i & 63] = W[i];
    int base = blockIdx.x * 64;
    for (int i = tid; i < 64 * 64; i += 256) {
        int r = i >> 6, c = i & 63;
        int node = base + r;
        Xs[r][c] = (node < NN) ? x[node * 64 + c] : 0.f;
    }
    __syncthreads();
    int tx = tid & 63;       // out col
    int ty = tid >> 6;       // 0..3
    float acc[16];
    #pragma unroll
    for (int i = 0; i < 16; i++) acc[i] = 0.f;
    for (int k = 0; k < 64; k++) {
        float w = Ws[k][tx];
        #pragma unroll
        for (int i = 0; i < 16; i++) acc[i] += Xs[ty + 4 * i][k] * w;
    }
    #pragma unroll
    for (int i = 0; i < 16; i++) {
        int node = base + ty + 4 * i;
        if (node < NN) g_h1[node * 64 + tx] = acc[i];
    }
}

// ---- layer 1 attention logits per (node, head) ----
__global__ void k_alpha1(const float* __restrict__ asrc, const float* __restrict__ adst) {
    int idx = blockIdx.x * blockDim.x + threadIdx.x;
    if (idx >= NN * 4) return;
    int node = idx >> 2, head = idx & 3;
    const float4* hp = (const float4*)(g_h1 + node * 64 + head * 16);
    const float4* ap = (const float4*)(asrc + head * 16);
    const float4* dp = (const float4*)(adst + head * 16);
    float s = 0.f, d = 0.f;
    #pragma unroll
    for (int j = 0; j < 4; j++) {
        float4 h = hp[j], a = ap[j], b = dp[j];
        s += h.x * a.x + h.y * a.y + h.z * a.z + h.w * a.w;
        d += h.x * b.x + h.y * b.y + h.z * b.z + h.w * b.w;
    }
    g_as1[idx] = s;
    g_ad1[idx] = d;
}

// ---- global max reduce (layer 1, per head) ----
__global__ void k_maxred1() {
    int tid = blockIdx.x * blockDim.x + threadIdx.x;
    int stride = gridDim.x * blockDim.x;     // multiple of 4
    float ms = -INFINITY, md = -INFINITY;
    for (int i = tid; i < NN * 4; i += stride) {
        ms = fmaxf(ms, g_as1[i]);
        md = fmaxf(md, g_ad1[i]);
    }
    // lanes with same (lane&3) hold same head
    #pragma unroll
    for (int off = 16; off >= 4; off >>= 1) {
        ms = fmaxf(ms, __shfl_xor_sync(0xffffffffu, ms, off));
        md = fmaxf(md, __shfl_xor_sync(0xffffffffu, md, off));
    }
    __shared__ float ss[8][4], sd[8][4];
    int warp = threadIdx.x >> 5, lane = threadIdx.x & 31;
    if (lane < 4) { ss[warp][lane] = ms; sd[warp][lane] = md; }
    __syncthreads();
    if (threadIdx.x < 4) {
        float a = -INFINITY, b = -INFINITY;
        for (int w = 0; w < 8; w++) {
            a = fmaxf(a, ss[w][threadIdx.x]);
            b = fmaxf(b, sd[w][threadIdx.x]);
        }
        atomicMaxF(&g_red[threadIdx.x], a);
        atomicMaxF(&g_red[4 + threadIdx.x], b);
    }
}

__global__ void k_M1() {
    int t = threadIdx.x;
    if (t < 4) g_M[t] = lrelu(g_red[t] + g_red[4 + t], ATT_SLOPE);
}

// ---- layer 1 denominator: edges then self-loops ----
__global__ void k_edgeB1() {
    int e = blockIdx.x * blockDim.x + threadIdx.x;
    if (e >= EE) return;
    int s = g_src[e], d = g_dst[e];
    float4 as = *(const float4*)(g_as1 + s * 4);
    float4 ad = *(const float4*)(g_ad1 + d * 4);
    float4 M = *(const float4*)(g_M);
    float4 w;
    w.x = __expf(lrelu(as.x + ad.x, ATT_SLOPE) - M.x);
    w.y = __expf(lrelu(as.y + ad.y, ATT_SLOPE) - M.y);
    w.z = __expf(lrelu(as.z + ad.z, ATT_SLOPE) - M.z);
    w.w = __expf(lrelu(as.w + ad.w, ATT_SLOPE) - M.w);
    atomicAdd((float4*)(g_den1 + d * 4), w);
}

__global__ void k_selfB1() {
    int idx = blockIdx.x * blockDim.x + threadIdx.x;
    if (idx >= NN * 4) return;
    g_den1[idx] += __expf(lrelu(g_as1[idx] + g_ad1[idx], ATT_SLOPE) - g_M[idx & 3]);
}

// ---- layer 1 weighted scatter: 16 lanes per edge, one float4 each ----
__global__ void k_edgeC1() {
    int gid = blockIdx.x * blockDim.x + threadIdx.x;
    int e = gid >> 4;
    if (e >= EE) return;
    int lane16 = threadIdx.x & 15;
    int head = lane16 >> 2;
    int s = g_src[e], d = g_dst[e];
    float as = g_as1[s * 4 + head];
    float ad = g_ad1[d * 4 + head];
    float den = g_den1[d * 4 + head];
    float alpha = __expf(lrelu(as + ad, ATT_SLOPE) - g_M[head]) / den;
    float4 hv = *(const float4*)(g_h1 + s * 64 + lane16 * 4);
    hv.x *= alpha; hv.y *= alpha; hv.z *= alpha; hv.w *= alpha;
    atomicAdd((float4*)(g_out1 + d * 64 + lane16 * 4), hv);
}

// ---- layer 1 epilogue: self-loop contribution + bias + leaky ----
__global__ void k_post1(const float* __restrict__ b1) {
    int idx = blockIdx.x * blockDim.x + threadIdx.x;
    if (idx >= NN * 16) return;
    int node = idx >> 4, c4 = idx & 15, head = c4 >> 2;
    int nh = node * 4 + head;
    float alpha = __expf(lrelu(g_as1[nh] + g_ad1[nh], ATT_SLOPE) - g_M[head]) / g_den1[nh];
    float4 o = ((float4*)g_out1)[idx];
    float4 h = ((const float4*)g_h1)[idx];
    float4 b = ((const float4*)b1)[c4];
    o.x = lrelu(o.x + h.x * alpha + b.x, ACT_SLOPE);
    o.y = lrelu(o.y + h.y * alpha + b.y, ACT_SLOPE);
    o.z = lrelu(o.z + h.z * alpha + b.z, ACT_SLOPE);
    o.w = lrelu(o.w + h.w * alpha + b.w, ACT_SLOPE);
    ((float4*)g_out1)[idx] = o;
}

// ---- layer 2 GEMM: h2 = act1 @ W2 (64 -> 16) ----
__global__ void k_gemm2(const float* __restrict__ W) {
    __shared__ float Ws[64][16];
    __shared__ float Xs[64][64];
    int tid = threadIdx.x;
    for (int i = tid; i < 64 * 16; i += 256) Ws[i >> 4][i & 15] = W[i];
    int base = blockIdx.x * 64;
    for (int i = tid; i < 64 * 64; i += 256) {
        int r = i >> 6, c = i & 63;
        int node = base + r;
        Xs[r][c] = (node < NN) ? g_out1[node * 64 + c] : 0.f;
    }
    __syncthreads();
    int tx = tid & 15;       // out col
    int ty = tid >> 4;       // 0..15
    float acc[4] = {0.f, 0.f, 0.f, 0.f};
    for (int k = 0; k < 64; k++) {
        float w = Ws[k][tx];
        #pragma unroll
        for (int i = 0; i < 4; i++) acc[i] += Xs[ty + 16 * i][k] * w;
    }
    #pragma unroll
    for (int i = 0; i < 4; i++) {
        int node = base + ty + 16 * i;
        if (node < NN) g_h2[node * 16 + tx] = acc[i];
    }
}

__global__ void k_alpha2(const float* __restrict__ asrc, const float* __restrict__ adst) {
    int node = blockIdx.x * blockDim.x + threadIdx.x;
    if (node >= NN) return;
    const float4* hp = (const float4*)(g_h2 + node * 16);
    const float4* ap = (const float4*)asrc;
    const float4* dp = (const float4*)adst;
    float s = 0.f, d = 0.f;
    #pragma unroll
    for (int j = 0; j < 4; j++) {
        float4 h = hp[j], a = ap[j], b = dp[j];
        s += h.x * a.x + h.y * a.y + h.z * a.z + h.w * a.w;
        d += h.x * b.x + h.y * b.y + h.z * b.z + h.w * b.w;
    }
    g_as2[node] = s;
    g_ad2[node] = d;
}

__global__ void k_maxred2() {
    int tid = blockIdx.x * blockDim.x + threadIdx.x;
    int stride = gridDim.x * blockDim.x;
    float ms = -INFINITY, md = -INFINITY;
    for (int i = tid; i < NN; i += stride) {
        ms = fmaxf(ms, g_as2[i]);
        md = fmaxf(md, g_ad2[i]);
    }
    #pragma unroll
    for (int off = 16; off >= 1; off >>= 1) {
        ms = fmaxf(ms, __shfl_xor_sync(0xffffffffu, ms, off));
        md = fmaxf(md, __shfl_xor_sync(0xffffffffu, md, off));
    }
    __shared__ float ss[8], sd[8];
    int warp = threadIdx.x >> 5, lane = threadIdx.x & 31;
    if (lane == 0) { ss[warp] = ms; sd[warp] = md; }
    __syncthreads();
    if (threadIdx.x == 0) {
        float a = -INFINITY, b = -INFINITY;
        for (int w = 0; w < 8; w++) { a = fmaxf(a, ss[w]); b = fmaxf(b, sd[w]); }
        atomicMaxF(&g_red[8], a);
        atomicMaxF(&g_red[9], b);
    }
}

__global__ void k_M2() {
    g_M[4] = lrelu(g_red[8] + g_red[9], ATT_SLOPE);
}

__global__ void k_edgeB2() {
    int e = blockIdx.x * blockDim.x + threadIdx.x;
    if (e >= EE) return;
    int s = g_src[e], d = g_dst[e];
    float w = __expf(lrelu(g_as2[s] + g_ad2[d], ATT_SLOPE) - g_M[4]);
    atomicAdd(&g_den2[d], w);
}

__global__ void k_selfB2() {
    int node = blockIdx.x * blockDim.x + threadIdx.x;
    if (node >= NN) return;
    g_den2[node] += __expf(lrelu(g_as2[node] + g_ad2[node], ATT_SLOPE) - g_M[4]);
}

// ---- layer 2 weighted scatter: 4 lanes per edge ----
__global__ void k_edgeC2() {
    int gid = blockIdx.x * blockDim.x + threadIdx.x;
    int e = gid >> 2;
    if (e >= EE) return;
    int lane4 = threadIdx.x & 3;
    int s = g_src[e], d = g_dst[e];
    float alpha = __expf(lrelu(g_as2[s] + g_ad2[d], ATT_SLOPE) - g_M[4]) / g_den2[d];
    float4 hv = ((const float4*)(g_h2 + s * 16))[lane4];
    hv.x *= alpha; hv.y *= alpha; hv.z *= alpha; hv.w *= alpha;
    atomicAdd(((float4*)(g_out2 + d * 16)) + lane4, hv);
}

// ---- final: self-loop + bias + leaky + linear -> out ----
__global__ void k_final(const float* __restrict__ b2, const float* __restrict__ Wo,
                        const float* __restrict__ bo, float* __restrict__ out) {
    int node = blockIdx.x * blockDim.x + threadIdx.x;
    if (node >= NN) return;
    float alpha = __expf(lrelu(g_as2[node] + g_ad2[node], ATT_SLOPE) - g_M[4]) / g_den2[node];
    const float4* Wo4 = (const float4*)Wo;
    const float4* b24 = (const float4*)b2;
    float acc = 0.f;
    #pragma unroll
    for (int j = 0; j < 4; j++) {
        float4 o = ((float4*)g_out2)[node * 4 + j];
        float4 h = ((const float4*)g_h2)[node * 4 + j];
        float4 b = b24[j];
        float4 w = Wo4[j];
        acc += lrelu(o.x + h.x * alpha + b.x, ACT_SLOPE) * w.x;
        acc += lrelu(o.y + h.y * alpha + b.y, ACT_SLOPE) * w.y;
        acc += lrelu(o.z + h.z * alpha + b.z, ACT_SLOPE) * w.z;
        acc += lrelu(o.w + h.w * alpha + b.w, ACT_SLOPE) * w.w;
    }
    out[node] = acc + bo[0];
}

extern "C" void kernel_launch(void* const* d_in, const int* in_sizes, int n_in,
                              void* d_out, int out_size) {
    const float* x   = (const float*)d_in[0];
    const void*  ei  = d_in[1];
    const float* W1  = (const float*)d_in[2];
    const float* a_s1 = (const float*)d_in[3];
    const float* a_d1 = (const float*)d_in[4];
    const float* b1  = (const float*)d_in[5];
    const float* W2  = (const float*)d_in[6];
    const float* a_s2 = (const float*)d_in[7];
    const float* a_d2 = (const float*)d_in[8];
    const float* b2  = (const float*)d_in[9];
    const float* Wo  = (const float*)d_in[10];
    const float* bo  = (const float*)d_in[11];
    float* out = (float*)d_out;

    k_detect<<<1, 256>>>((const long long*)ei);
    k_convert<<<(EE + 255) / 256, 256>>>(ei);
    k_init<<<(NN * 16 + 255) / 256, 256>>>();

    // layer 1
    k_gemm1<<<(NN + 63) / 64, 256>>>(x, W1);
    k_alpha1<<<(NN * 4 + 255) / 256, 256>>>(a_s1, a_d1);
    k_maxred1<<<200, 256>>>();
    k_M1<<<1, 32>>>();
    k_edgeB1<<<(EE + 255) / 256, 256>>>();
    k_selfB1<<<(NN * 4 + 255) / 256, 256>>>();
    k_edgeC1<<<(EE * 16 + 255) / 256, 256>>>();
    k_post1<<<(NN * 16 + 255) / 256, 256>>>(b1);

    // layer 2
    k_gemm2<<<(NN + 63) / 64, 256>>>(W2);
    k_alpha2<<<(NN + 255) / 256, 256>>>(a_s2, a_d2);
    k_maxred2<<<200, 256>>>();
    k_M2<<<1, 1>>>();
    k_edgeB2<<<(EE + 255) / 256, 256>>>();
    k_selfB2<<<(NN + 255) / 256, 256>>>();
    k_edgeC2<<<(EE * 4 + 255) / 256, 256>>>();

    k_final<<<(NN + 255) / 256, 256>>>(b2, Wo, bo, out);
}

// round 3
// speedup vs baseline: 1.3425x; 1.3244x over previous
#include <cuda_runtime.h>
#include <cuda_bf16.h>
#include <math.h>

// ----------------------------------------------------------------------------
// GAT_cat_decoder: 2-layer GATConv (PyG, add_self_loops) + linear.
// N=50000, E=1600000, IN=64, HID=16, HEADS=4, OUT=1.
// R2: fused numerator+denominator edge pass (global-shift softmax makes the
// division deferrable), register-blocked GEMMs, int2-packed edges.
// ----------------------------------------------------------------------------

#define NN 50000
#define EE 1600000
#define ATT_SLOPE 0.2f
#define ACT_SLOPE 0.01f

// ---- device scratch (static, no allocation) ----
__device__ __align__(16) float g_h1[NN * 64];
__device__ __align__(16) float g_out1[NN * 64];
__device__ __align__(16) float g_as1[NN * 4];
__device__ __align__(16) float g_ad1[NN * 4];
__device__ __align__(16) float g_den1[NN * 4];
__device__ __align__(16) float g_h2[NN * 16];
__device__ __align__(16) float g_out2[NN * 16];
__device__ __align__(16) float g_as2[NN];
__device__ __align__(16) float g_ad2[NN];
__device__ __align__(16) float g_den2[NN];
__device__ __align__(8)  int2  g_edge[EE];
// reduction scratch: [0..3] max_as1, [4..7] max_ad1, [8] max_as2, [9] max_ad2
__device__ float g_red[12];
// shifts: [0..3] M1 per head, [4] M2
__device__ __align__(16) float g_M[8];
__device__ int g_is64;

__device__ __forceinline__ float lrelu(float x, float s) {
    return x > 0.f ? x : s * x;
}

__device__ __forceinline__ void atomicMaxF(float* a, float v) {
    if (v >= 0.f) atomicMax((int*)a, __float_as_int(v));
    else          atomicMin((unsigned int*)a, __float_as_uint(v));
}

// ---- edge index dtype detection + conversion ----
__global__ void k_detect(const long long* __restrict__ e) {
    int t = threadIdx.x;
    int bad = 0;
    const int SAMPLES = 2048;
    long long stride = (long long)EE / SAMPLES;
    for (int i = t; i < SAMPLES; i += 256) {
        long long v = e[(long long)i * stride];
        if (v < 0 || v >= NN) bad = 1;
    }
    bad = __syncthreads_or(bad);
    if (t == 0) g_is64 = bad ? 0 : 1;
}

__global__ void k_convert(const void* __restrict__ eraw) {
    int i = blockIdx.x * blockDim.x + threadIdx.x;
    if (i >= EE) return;
    int s, d;
    if (g_is64) {
        const long long* e = (const long long*)eraw;
        s = (int)e[i];
        d = (int)e[EE + i];
    } else {
        const int* e = (const int*)eraw;
        s = e[i];
        d = e[EE + i];
    }
    g_edge[i] = make_int2(s, d);
}

// ---- per-launch state reset ----
__global__ void k_init() {
    int i = blockIdx.x * blockDim.x + threadIdx.x;
    float4 z = make_float4(0.f, 0.f, 0.f, 0.f);
    if (i < NN * 16) ((float4*)g_out1)[i] = z;   // NN*64 floats
    if (i < NN * 4)  ((float4*)g_out2)[i] = z;   // NN*16 floats
    if (i < NN)      ((float4*)g_den1)[i] = z;   // NN*4 floats
    if (i < NN)      g_den2[i] = 0.f;
    if (i < 12)      g_red[i] = -INFINITY;
}

// ---- layer 1 GEMM: h1 = x @ W1 (64 -> 64), 128-row tiles, 8x4 per thread ----
__global__ __launch_bounds__(256) void k_gemm1(const float* __restrict__ x,
                                               const float* __restrict__ W) {
    __shared__ float4 Ws[64][16];    // [k][col4]   16 KB
    __shared__ float4 Xs[128][16];   // [row][k4]   32 KB
    int tid = threadIdx.x;           // 256
    for (int i = tid; i < 64 * 16; i += 256) {
        Ws[i >> 4][i & 15] = ((const float4*)W)[i];
    }
    int base = blockIdx.x * 128;
    for (int i = tid; i < 128 * 16; i += 256) {
        int r = i >> 4, k4 = i & 15;
        int node = base + r;
        Xs[r][k4] = (node < NN) ? ((const float4*)x)[node * 16 + k4]
                                : make_float4(0.f, 0.f, 0.f, 0.f);
    }
    __syncthreads();
    int tx = tid & 15;   // col group: cols tx*4..+3
    int ty = tid >> 4;   // row group: rows ty*8..+7
    float acc[8][4];
    #pragma unroll
    for (int j = 0; j < 8; j++)
        #pragma unroll
        for (int c = 0; c < 4; c++) acc[j][c] = 0.f;

    #pragma unroll 4
    for (int k4 = 0; k4 < 16; k4++) {
        float4 w0 = Ws[k4 * 4 + 0][tx];
        float4 w1 = Ws[k4 * 4 + 1][tx];
        float4 w2 = Ws[k4 * 4 + 2][tx];
        float4 w3 = Ws[k4 * 4 + 3][tx];
        #pragma unroll
        for (int j = 0; j < 8; j++) {
            float4 xv = Xs[ty * 8 + j][k4];
            acc[j][0] += xv.x * w0.x + xv.y * w1.x + xv.z * w2.x + xv.w * w3.x;
            acc[j][1] += xv.x * w0.y + xv.y * w1.y + xv.z * w2.y + xv.w * w3.y;
            acc[j][2] += xv.x * w0.z + xv.y * w1.z + xv.z * w2.z + xv.w * w3.z;
            acc[j][3] += xv.x * w0.w + xv.y * w1.w + xv.z * w2.w + xv.w * w3.w;
        }
    }
    #pragma unroll
    for (int j = 0; j < 8; j++) {
        int node = base + ty * 8 + j;
        if (node < NN) {
            float4 o = make_float4(acc[j][0], acc[j][1], acc[j][2], acc[j][3]);
            ((float4*)g_h1)[node * 16 + tx] = o;
        }
    }
}

// ---- layer 1 attention logits per (node, head) ----
__global__ void k_alpha1(const float* __restrict__ asrc, const float* __restrict__ adst) {
    int idx = blockIdx.x * blockDim.x + threadIdx.x;
    if (idx >= NN * 4) return;
    int node = idx >> 2, head = idx & 3;
    const float4* hp = (const float4*)(g_h1 + node * 64 + head * 16);
    const float4* ap = (const float4*)(asrc + head * 16);
    const float4* dp = (const float4*)(adst + head * 16);
    float s = 0.f, d = 0.f;
    #pragma unroll
    for (int j = 0; j < 4; j++) {
        float4 h = hp[j], a = ap[j], b = dp[j];
        s += h.x * a.x + h.y * a.y + h.z * a.z + h.w * a.w;
        d += h.x * b.x + h.y * b.y + h.z * b.z + h.w * b.w;
    }
    g_as1[idx] = s;
    g_ad1[idx] = d;
}

// ---- global max reduce (layer 1, per head) ----
__global__ void k_maxred1() {
    int tid = blockIdx.x * blockDim.x + threadIdx.x;
    int stride = gridDim.x * blockDim.x;   // multiple of 4
    float ms = -INFINITY, md = -INFINITY;
    for (int i = tid; i < NN * 4; i += stride) {
        ms = fmaxf(ms, g_as1[i]);
        md = fmaxf(md, g_ad1[i]);
    }
    #pragma unroll
    for (int off = 16; off >= 4; off >>= 1) {
        ms = fmaxf(ms, __shfl_xor_sync(0xffffffffu, ms, off));
        md = fmaxf(md, __shfl_xor_sync(0xffffffffu, md, off));
    }
    __shared__ float ss[8][4], sd[8][4];
    int warp = threadIdx.x >> 5, lane = threadIdx.x & 31;
    if (lane < 4) { ss[warp][lane] = ms; sd[warp][lane] = md; }
    __syncthreads();
    if (threadIdx.x < 4) {
        float a = -INFINITY, b = -INFINITY;
        for (int w = 0; w < 8; w++) {
            a = fmaxf(a, ss[w][threadIdx.x]);
            b = fmaxf(b, sd[w][threadIdx.x]);
        }
        atomicMaxF(&g_red[threadIdx.x], a);
        atomicMaxF(&g_red[4 + threadIdx.x], b);
    }
}

__global__ void k_M1() {
    int t = threadIdx.x;
    if (t < 4) g_M[t] = lrelu(g_red[t] + g_red[4 + t], ATT_SLOPE);
}

// ---- layer 1 fused edge pass: numerator + denominator in one sweep ----
__global__ void k_edge1() {
    int gid = blockIdx.x * blockDim.x + threadIdx.x;
    int e = gid >> 4;
    if (e >= EE) return;
    int lane = threadIdx.x & 15;
    int head = lane >> 2;
    int2 ed = g_edge[e];
    int s = ed.x, d = ed.y;
    float as = g_as1[s * 4 + head];
    float ad = g_ad1[d * 4 + head];
    float w = __expf(lrelu(as + ad, ATT_SLOPE) - g_M[head]);
    float4 hv = *(const float4*)(g_h1 + s * 64 + lane * 4);
    hv.x *= w; hv.y *= w; hv.z *= w; hv.w *= w;
    atomicAdd((float4*)(g_out1 + d * 64 + lane * 4), hv);
    if ((lane & 3) == 0) atomicAdd(&g_den1[d * 4 + head], w);
}

// ---- layer 1 epilogue: add self-loop, divide, bias, leaky ----
__global__ void k_post1(const float* __restrict__ b1) {
    int idx = blockIdx.x * blockDim.x + threadIdx.x;
    if (idx >= NN * 16) return;
    int node = idx >> 4, c4 = idx & 15, head = c4 >> 2;
    int nh = node * 4 + head;
    float w = __expf(lrelu(g_as1[nh] + g_ad1[nh], ATT_SLOPE) - g_M[head]);
    float inv = 1.f / (g_den1[nh] + w);
    float4 o = ((float4*)g_out1)[idx];
    float4 h = ((const float4*)g_h1)[idx];
    float4 b = ((const float4*)b1)[c4];
    o.x = lrelu((o.x + h.x * w) * inv + b.x, ACT_SLOPE);
    o.y = lrelu((o.y + h.y * w) * inv + b.y, ACT_SLOPE);
    o.z = lrelu((o.z + h.z * w) * inv + b.z, ACT_SLOPE);
    o.w = lrelu((o.w + h.w * w) * inv + b.w, ACT_SLOPE);
    ((float4*)g_out1)[idx] = o;
}

// ---- layer 2 GEMM: h2 = act1 @ W2 (64 -> 16), 128-row tiles, 8x1 per thread ----
__global__ __launch_bounds__(256) void k_gemm2(const float* __restrict__ W) {
    __shared__ float Ws[64 * 16];    // [k][col]  4 KB
    __shared__ float4 Xs[128][16];   // [row][k4] 32 KB
    int tid = threadIdx.x;
    for (int i = tid; i < 64 * 16; i += 256) Ws[i] = W[i];
    int base = blockIdx.x * 128;
    for (int i = tid; i < 128 * 16; i += 256) {
        int r = i >> 4, k4 = i & 15;
        int node = base + r;
        Xs[r][k4] = (node < NN) ? ((const float4*)g_out1)[node * 16 + k4]
                                : make_float4(0.f, 0.f, 0.f, 0.f);
    }
    __syncthreads();
    int tx = tid & 15;   // out col
    int ty = tid >> 4;   // row group: rows ty*8..+7
    float acc[8];
    #pragma unroll
    for (int j = 0; j < 8; j++) acc[j] = 0.f;

    #pragma unroll 4
    for (int k4 = 0; k4 < 16; k4++) {
        float w0 = Ws[(k4 * 4 + 0) * 16 + tx];
        float w1 = Ws[(k4 * 4 + 1) * 16 + tx];
        float w2 = Ws[(k4 * 4 + 2) * 16 + tx];
        float w3 = Ws[(k4 * 4 + 3) * 16 + tx];
        #pragma unroll
        for (int j = 0; j < 8; j++) {
            float4 xv = Xs[ty * 8 + j][k4];
            acc[j] += xv.x * w0 + xv.y * w1 + xv.z * w2 + xv.w * w3;
        }
    }
    #pragma unroll
    for (int j = 0; j < 8; j++) {
        int node = base + ty * 8 + j;
        if (node < NN) g_h2[node * 16 + tx] = acc[j];
    }
}

__global__ void k_alpha2(const float* __restrict__ asrc, const float* __restrict__ adst) {
    int node = blockIdx.x * blockDim.x + threadIdx.x;
    if (node >= NN) return;
    const float4* hp = (const float4*)(g_h2 + node * 16);
    const float4* ap = (const float4*)asrc;
    const float4* dp = (const float4*)adst;
    float s = 0.f, d = 0.f;
    #pragma unroll
    for (int j = 0; j < 4; j++) {
        float4 h = hp[j], a = ap[j], b = dp[j];
        s += h.x * a.x + h.y * a.y + h.z * a.z + h.w * a.w;
        d += h.x * b.x + h.y * b.y + h.z * b.z + h.w * b.w;
    }
    g_as2[node] = s;
    g_ad2[node] = d;
}

__global__ void k_maxred2() {
    int tid = blockIdx.x * blockDim.x + threadIdx.x;
    int stride = gridDim.x * blockDim.x;
    float ms = -INFINITY, md = -INFINITY;
    for (int i = tid; i < NN; i += stride) {
        ms = fmaxf(ms, g_as2[i]);
        md = fmaxf(md, g_ad2[i]);
    }
    #pragma unroll
    for (int off = 16; off >= 1; off >>= 1) {
        ms = fmaxf(ms, __shfl_xor_sync(0xffffffffu, ms, off));
        md = fmaxf(md, __shfl_xor_sync(0xffffffffu, md, off));
    }
    __shared__ float ss[8], sd[8];
    int warp = threadIdx.x >> 5, lane = threadIdx.x & 31;
    if (lane == 0) { ss[warp] = ms; sd[warp] = md; }
    __syncthreads();
    if (threadIdx.x == 0) {
        float a = -INFINITY, b = -INFINITY;
        for (int w = 0; w < 8; w++) { a = fmaxf(a, ss[w]); b = fmaxf(b, sd[w]); }
        atomicMaxF(&g_red[8], a);
        atomicMaxF(&g_red[9], b);
    }
}

__global__ void k_M2() {
    g_M[4] = lrelu(g_red[8] + g_red[9], ATT_SLOPE);
}

// ---- layer 2 fused edge pass ----
__global__ void k_edge2() {
    int gid = blockIdx.x * blockDim.x + threadIdx.x;
    int e = gid >> 2;
    if (e >= EE) return;
    int lane = threadIdx.x & 3;
    int2 ed = g_edge[e];
    int s = ed.x, d = ed.y;
    float w = __expf(lrelu(g_as2[s] + g_ad2[d], ATT_SLOPE) - g_M[4]);
    float4 hv = ((const float4*)(g_h2 + s * 16))[lane];
    hv.x *= w; hv.y *= w; hv.z *= w; hv.w *= w;
    atomicAdd(((float4*)(g_out2 + d * 16)) + lane, hv);
    if (lane == 0) atomicAdd(&g_den2[d], w);
}

// ---- final: self-loop + divide + bias + leaky + linear -> out ----
__global__ void k_final(const float* __restrict__ b2, const float* __restrict__ Wo,
                        const float* __restrict__ bo, float* __restrict__ out) {
    int node = blockIdx.x * blockDim.x + threadIdx.x;
    if (node >= NN) return;
    float w = __expf(lrelu(g_as2[node] + g_ad2[node], ATT_SLOPE) - g_M[4]);
    float inv = 1.f / (g_den2[node] + w);
    const float4* Wo4 = (const float4*)Wo;
    const float4* b24 = (const float4*)b2;
    float acc = 0.f;
    #pragma unroll
    for (int j = 0; j < 4; j++) {
        float4 o = ((float4*)g_out2)[node * 4 + j];
        float4 h = ((const float4*)g_h2)[node * 4 + j];
        float4 b = b24[j];
        float4 ww = Wo4[j];
        acc += lrelu((o.x + h.x * w) * inv + b.x, ACT_SLOPE) * ww.x;
        acc += lrelu((o.y + h.y * w) * inv + b.y, ACT_SLOPE) * ww.y;
        acc += lrelu((o.z + h.z * w) * inv + b.z, ACT_SLOPE) * ww.z;
        acc += lrelu((o.w + h.w * w) * inv + b.w, ACT_SLOPE) * ww.w;
    }
    out[node] = acc + bo[0];
}

extern "C" void kernel_launch(void* const* d_in, const int* in_sizes, int n_in,
                              void* d_out, int out_size) {
    const float* x    = (const float*)d_in[0];
    const void*  ei   = d_in[1];
    const float* W1   = (const float*)d_in[2];
    const float* a_s1 = (const float*)d_in[3];
    const float* a_d1 = (const float*)d_in[4];
    const float* b1   = (const float*)d_in[5];
    const float* W2   = (const float*)d_in[6];
    const float* a_s2 = (const float*)d_in[7];
    const float* a_d2 = (const float*)d_in[8];
    const float* b2   = (const float*)d_in[9];
    const float* Wo   = (const float*)d_in[10];
    const float* bo   = (const float*)d_in[11];
    float* out = (float*)d_out;

    k_detect<<<1, 256>>>((const long long*)ei);
    k_convert<<<(EE + 255) / 256, 256>>>(ei);
    k_init<<<(NN * 16 + 255) / 256, 256>>>();

    // layer 1
    k_gemm1<<<(NN + 127) / 128, 256>>>(x, W1);
    k_alpha1<<<(NN * 4 + 255) / 256, 256>>>(a_s1, a_d1);
    k_maxred1<<<200, 256>>>();
    k_M1<<<1, 32>>>();
    k_edge1<<<(EE * 16 + 255) / 256, 256>>>();
    k_post1<<<(NN * 16 + 255) / 256, 256>>>(b1);

    // layer 2
    k_gemm2<<<(NN + 127) / 128, 256>>>(W2);
    k_alpha2<<<(NN + 255) / 256, 256>>>(a_s2, a_d2);
    k_maxred2<<<200, 256>>>();
    k_M2<<<1, 1>>>();
    k_edge2<<<(EE * 4 + 255) / 256, 256>>>();

    k_final<<<(NN + 255) / 256, 256>>>(b2, Wo, bo, out);
}